// round 15
// baseline (speedup 1.0000x reference)
#include <cuda_runtime.h>
#include <cuda_bf16.h>
#include <math.h>
#include <stdint.h>

// ---------------- problem constants ----------------
#define CC    16
#define TT    2000
#define EE    256
#define NFFT  200
#define HOPL  100
#define NF    101
#define NFR   19
#define SEQ   (CC*NFR)   // 304
#define DEPTH 4
#define FF4   1024
#define HH    8
#define DH    32
#define BMAX  256
#define MMAX  (BMAX*SEQ)   // 77824
#define NQKV  768

// ---------------- device scratch ----------------
__device__ float          g_H  [ (size_t)MMAX*EE ];
__device__ __nv_bfloat16  g_Yb [ (size_t)MMAX*EE ];
__device__ __nv_bfloat16  g_QKV[ (size_t)MMAX*NQKV ];
__device__ __nv_bfloat16  g_Ob [ (size_t)MMAX*EE ];
__device__ __nv_bfloat16  g_FFb[ (size_t)MMAX*FF4 ];
__device__ __nv_bfloat16  g_D  [ (size_t)MMAX*EE ];
__device__ float          g_CTX[ (size_t)BMAX*HH*DH*DH ];
__device__ float g_cosT[ NFFT*NF ];
__device__ float g_sinT[ NFFT*NF ];
__device__ float g_win [ NFFT ];
__device__ float g_pe  [ NFR*EE ];
#define LWT  (4*65536 + 262144 + 262144)
__device__ __nv_bfloat16 g_Wt[ (size_t)DEPTH * LWT ];

__device__ __forceinline__ uint32_t smem_u32(const void* p) {
    uint32_t a;
    asm("{ .reg .u64 t; cvta.to.shared.u64 t, %1; cvt.u32.u64 %0, t; }" : "=r"(a) : "l"(p));
    return a;
}

// ------------- ONE setup kernel: transposes + twiddles + PE table -----------
__device__ __forceinline__ void transpose_tile(
    const float* __restrict__ s, __nv_bfloat16* __restrict__ d,
    int R, int C, int bx, int by, float tsh[32][33])
{
    int x = threadIdx.x, y = threadIdx.y;
    #pragma unroll
    for (int i = 0; i < 32; i += 8)
        tsh[y + i][x] = s[(size_t)(by*32 + y + i) * C + bx*32 + x];
    __syncthreads();
    #pragma unroll
    for (int i = 0; i < 32; i += 8)
        d[(size_t)(bx*32 + y + i) * R + by*32 + x] = __float2bfloat16_rn(tsh[x][y + i]);
}

__global__ void setup_kernel(const float* Wq, const float* Wk,
                             const float* Wv, const float* Wo,
                             const float* W1, const float* W2)
{
    __shared__ float t[32][33];
    int z = blockIdx.z;
    int bx = blockIdx.x, by = blockIdx.y;
    if (z < 16) {
        if (bx >= 8 || by >= 8) return;
        int l = z >> 2, which = z & 3;
        const float* srcs[4] = {Wq, Wk, Wv, Wo};
        const float* s = srcs[which] + (size_t)l * 65536;
        __nv_bfloat16* d = g_Wt + (size_t)l * LWT + (size_t)which * 65536;
        transpose_tile(s, d, 256, 256, bx, by, t);
    } else if (z < 20) {
        if (by >= 8) return;
        int l = z - 16;
        const float* s = W1 + (size_t)l * 262144;
        __nv_bfloat16* d = g_Wt + (size_t)l * LWT + 262144;
        transpose_tile(s, d, 256, 1024, bx, by, t);
    } else if (z < 24) {
        if (bx >= 8) return;
        int l = z - 20;
        const float* s = W2 + (size_t)l * 262144;
        __nv_bfloat16* d = g_Wt + (size_t)l * LWT + 524288;
        transpose_tile(s, d, 1024, 256, bx, by, t);
    } else {
        if (bx >= 8 || by >= 8) return;
        int tid = threadIdx.y * 32 + threadIdx.x;
        int bid = by * 8 + bx;
        int i0  = bid * 256 + tid;
        #pragma unroll
        for (int rep = 0; rep < 2; ++rep) {
            int i = i0 + rep * 16384;
            if (i < NFFT*NF) {
                int n = i / NF, k = i % NF;
                int m = (k * n) % NFFT;
                float a = (float)m / 100.0f;
                g_cosT[i] = cospif(a);
                g_sinT[i] = sinpif(a);
            }
        }
        if (i0 < NFFT) g_win[i0] = 0.5f * (1.0f - cospif((float)i0 / 100.0f));
        if (i0 < NFR*EE) {
            int f = i0 / EE, e = i0 % EE;
            int j2 = e & ~1;
            float dv = expf((float)j2 * (-9.210340371976184f / (float)EE));
            float arg = (float)f * dv;
            g_pe[i0] = (e & 1) ? cosf(arg) : sinf(arg);
        }
    }
}

// ------- STFT + |.| + projection + tokens + PE(table), fused layer-0 LN ----
__global__ void __launch_bounds__(256) embed_ln_kernel(
    const float* __restrict__ x, const int* __restrict__ noff_p,
    const float* __restrict__ projW, const float* __restrict__ projb,
    const float* __restrict__ chan_tok,
    const float* __restrict__ ln_g, const float* __restrict__ ln_b)
{
    __shared__ float frs[8][NFFT];
    __shared__ float pre[2][8][NF+1];
    __shared__ float pim[2][8][NF+1];
    __shared__ float mags[8][NF+3];
    __shared__ float hrows[8][EE];
    int tid  = threadIdx.x;
    int base = blockIdx.x * 8;

    for (int i = tid; i < 8*NFFT; i += 256) {
        int fl = i / NFFT, n = i % NFFT;
        int lid = base + fl;
        int b = lid / (CC*NFR); int rem = lid % (CC*NFR);
        int c = rem / NFR;      int f = rem % NFR;
        frs[fl][n] = x[((size_t)b*CC + c)*TT + f*HOPL + n] * g_win[n];
    }
    __syncthreads();

    if (tid < 2*NF) {
        int half = (tid >= NF) ? 1 : 0;
        int k = tid - half*NF;
        float re[8] = {0,0,0,0,0,0,0,0}, im[8] = {0,0,0,0,0,0,0,0};
        int n0 = half * 100;
        for (int n = n0; n < n0 + 100; ++n) {
            float cv = g_cosT[n*NF + k];
            float sv = g_sinT[n*NF + k];
            #pragma unroll
            for (int fl = 0; fl < 8; ++fl) {
                float fv = frs[fl][n];
                re[fl] = fmaf(fv, cv, re[fl]);
                im[fl] = fmaf(fv, sv, im[fl]);
            }
        }
        #pragma unroll
        for (int fl = 0; fl < 8; ++fl) {
            pre[half][fl][k] = re[fl];
            pim[half][fl][k] = im[fl];
        }
    }
    __syncthreads();

    if (tid < NF) {
        #pragma unroll
        for (int fl = 0; fl < 8; ++fl) {
            float re = pre[0][fl][tid] + pre[1][fl][tid];
            float im = pim[0][fl][tid] + pim[1][fl][tid];
            mags[fl][tid] = sqrtf(re*re + im*im);
        }
    }
    __syncthreads();

    int e = tid;
    float acc[8] = {0,0,0,0,0,0,0,0};
    for (int f = 0; f < NF; ++f) {
        float w = projW[f*EE + e];
        #pragma unroll
        for (int fl = 0; fl < 8; ++fl) acc[fl] = fmaf(mags[fl][f], w, acc[fl]);
    }
    int noff  = *noff_p;
    float pb  = projb[e];
    #pragma unroll
    for (int fl = 0; fl < 8; ++fl) {
        int lid = base + fl;
        int rem = lid % (CC*NFR);
        int c = rem / NFR; int f = rem % NFR;
        float pe  = g_pe[f*EE + e];
        float ct  = chan_tok[(size_t)(noff + c)*EE + e];
        float hv  = acc[fl] + pb + ct + pe;
        g_H[(size_t)lid*EE + e] = hv;
        hrows[fl][e] = hv;
    }
    __syncthreads();

    int w = tid >> 5, lane = tid & 31;
    float v[8]; float s = 0.f;
    #pragma unroll
    for (int i = 0; i < 8; ++i) { v[i] = hrows[w][lane + 32*i]; s += v[i]; }
    #pragma unroll
    for (int o = 16; o; o >>= 1) s += __shfl_xor_sync(0xffffffffu, s, o);
    float mu = s * (1.f/256.f);
    float q = 0.f;
    #pragma unroll
    for (int i = 0; i < 8; ++i) { float d = v[i]-mu; q = fmaf(d,d,q); }
    #pragma unroll
    for (int o = 16; o; o >>= 1) q += __shfl_xor_sync(0xffffffffu, q, o);
    float r = rsqrtf(q * (1.f/256.f) + 1e-5f);
    __nv_bfloat16* yr = g_Yb + (size_t)(base + w)*EE;
    #pragma unroll
    for (int i = 0; i < 8; ++i) {
        int c = lane + 32*i;
        yr[c] = __float2bfloat16_rn((v[i]-mu)*r*ln_g[c] + ln_b[c]);
    }
}

// ------- fused residual + LayerNorm: H += D + bias; Y = LN(H) ---------------
__global__ void resln_kernel(float* __restrict__ H, const __nv_bfloat16* __restrict__ D,
                             const float* __restrict__ bias,
                             __nv_bfloat16* __restrict__ Y,
                             const float* __restrict__ g, const float* __restrict__ b,
                             int rows)
{
    int w    = (blockIdx.x * blockDim.x + threadIdx.x) >> 5;
    int lane = threadIdx.x & 31;
    if (w >= rows) return;
    float* hr = H + (size_t)w*EE + lane*8;
    const __nv_bfloat16* dr = D + (size_t)w*EE + lane*8;
    float v[8];
    *(float4*)&v[0] = *(const float4*)(hr);
    *(float4*)&v[4] = *(const float4*)(hr + 4);
    uint4 du = *(const uint4*)dr;
    uint32_t dw[4] = {du.x, du.y, du.z, du.w};
    float bi[8];
    *(float4*)&bi[0] = *(const float4*)(bias + lane*8);
    *(float4*)&bi[4] = *(const float4*)(bias + lane*8 + 4);
    #pragma unroll
    for (int j = 0; j < 4; ++j) {
        float2 p = __bfloat1622float2(*reinterpret_cast<__nv_bfloat162*>(&dw[j]));
        v[2*j]   += p.x + bi[2*j];
        v[2*j+1] += p.y + bi[2*j+1];
    }
    *(float4*)(hr)     = *(float4*)&v[0];
    *(float4*)(hr + 4) = *(float4*)&v[4];

    float s = 0.f;
    #pragma unroll
    for (int i = 0; i < 8; ++i) s += v[i];
    #pragma unroll
    for (int o = 16; o; o >>= 1) s += __shfl_xor_sync(0xffffffffu, s, o);
    float mu = s * (1.f/256.f);
    float q = 0.f;
    #pragma unroll
    for (int i = 0; i < 8; ++i) { float d = v[i]-mu; q = fmaf(d,d,q); }
    #pragma unroll
    for (int o = 16; o; o >>= 1) q += __shfl_xor_sync(0xffffffffu, q, o);
    float r = rsqrtf(q * (1.f/256.f) + 1e-5f);
    float gg[8], bb[8];
    *(float4*)&gg[0] = *(const float4*)(g + lane*8);
    *(float4*)&gg[4] = *(const float4*)(g + lane*8 + 4);
    *(float4*)&bb[0] = *(const float4*)(b + lane*8);
    *(float4*)&bb[4] = *(const float4*)(b + lane*8 + 4);
    __nv_bfloat162 o2[4];
    #pragma unroll
    for (int i = 0; i < 4; ++i) {
        float y0 = (v[2*i]  -mu)*r*gg[2*i]   + bb[2*i];
        float y1 = (v[2*i+1]-mu)*r*gg[2*i+1] + bb[2*i+1];
        o2[i] = __float22bfloat162_rn(make_float2(y0, y1));
    }
    *(uint4*)(Y + (size_t)w*EE + lane*8) = *(uint4*)o2;
}

// == bf16 mma.sync GEMM, 512 thr / 16 warps (4x4), warp 32x32, K64, 3-stage ==
#define ROWB    144
#define TILEB   (128*ROWB)
#define STAGE_B (2*TILEB)
#define GSMEM   (3*STAGE_B)

__device__ __forceinline__ float gelu_exact(float x) {
    return 0.5f * x * (1.0f + erff(x * 0.70710678118654752f));
}

__device__ __forceinline__ void mma_bf16(float* c, uint32_t a0, uint32_t a1,
                                         uint32_t a2, uint32_t a3,
                                         uint32_t b0, uint32_t b1)
{
    asm volatile(
        "mma.sync.aligned.m16n8k16.row.col.f32.bf16.bf16.f32 "
        "{%0,%1,%2,%3}, {%4,%5,%6,%7}, {%8,%9}, {%0,%1,%2,%3};"
        : "+f"(c[0]), "+f"(c[1]), "+f"(c[2]), "+f"(c[3])
        : "r"(a0), "r"(a1), "r"(a2), "r"(a3), "r"(b0), "r"(b1));
}

__global__ void __launch_bounds__(512, 2) mma_gemm_kernel(
    const __nv_bfloat16* __restrict__ A, const __nv_bfloat16* __restrict__ Bt,
    __nv_bfloat16* __restrict__ C, const float* __restrict__ bias,
    int M, int N, int K, int mode)
{
    extern __shared__ char smraw[];
    uint32_t sb = smem_u32(smraw);
    int tid = threadIdx.x, lane = tid & 31, wid = tid >> 5;
    int bm = blockIdx.y, bn = blockIdx.x;
    int wm = wid >> 2, wn = wid & 3;    // 4x4 warp grid, 32x32 tiles

    const __nv_bfloat16* Ag = A  + (size_t)bm * 128 * K;
    const __nv_bfloat16* Bg = Bt + (size_t)bn * 128 * K;

    float acc[2][4][4];
    #pragma unroll
    for (int mt = 0; mt < 2; ++mt)
        #pragma unroll
        for (int nt = 0; nt < 4; ++nt)
            #pragma unroll
            for (int r = 0; r < 4; ++r) acc[mt][nt][r] = 0.f;

    auto copy_stage = [&](int t, int s) {
        uint32_t base = sb + s * STAGE_B;
        #pragma unroll
        for (int i = 0; i < 2; ++i) {
            int idx = tid + i*512;
            int row = idx >> 3, q = idx & 7;
            const __nv_bfloat16* sa = Ag + (size_t)row * K + t*64 + q*8;
            const __nv_bfloat16* sbp = Bg + (size_t)row * K + t*64 + q*8;
            uint32_t dA = base + row*ROWB + q*16;
            uint32_t dB = base + TILEB + row*ROWB + q*16;
            asm volatile("cp.async.cg.shared.global [%0], [%1], 16;" :: "r"(dA), "l"(sa) : "memory");
            asm volatile("cp.async.cg.shared.global [%0], [%1], 16;" :: "r"(dB), "l"(sbp) : "memory");
        }
    };

    int nc = K >> 6;
    copy_stage(0, 0);
    asm volatile("cp.async.commit_group;" ::: "memory");
    if (nc > 1) copy_stage(1, 1);
    asm volatile("cp.async.commit_group;" ::: "memory");

    for (int t = 0; t < nc; ++t) {
        asm volatile("cp.async.wait_group 1;" ::: "memory");
        __syncthreads();
        if (t + 2 < nc) copy_stage(t + 2, (t + 2) % 3);
        asm volatile("cp.async.commit_group;" ::: "memory");

        int s = t % 3;
        uint32_t Abase = sb + s*STAGE_B + (wm*32)*ROWB;
        uint32_t Bbase = sb + s*STAGE_B + TILEB + (wn*32)*ROWB;
        #pragma unroll
        for (int kk = 0; kk < 4; ++kk) {
            uint32_t af[2][4], bfr[2][4];
            #pragma unroll
            for (int mt = 0; mt < 2; ++mt) {
                uint32_t ad = Abase + (uint32_t)(mt*16 + (lane & 15))*ROWB
                            + (uint32_t)(lane >> 4)*16 + kk*32;
                asm volatile("ldmatrix.sync.aligned.m8n8.x4.shared.b16 {%0,%1,%2,%3}, [%4];"
                    : "=r"(af[mt][0]), "=r"(af[mt][1]), "=r"(af[mt][2]), "=r"(af[mt][3])
                    : "r"(ad));
            }
            #pragma unroll
            for (int ng = 0; ng < 2; ++ng) {
                uint32_t bd = Bbase + (uint32_t)(ng*16 + (lane & 7) + ((lane >> 4) & 1)*8)*ROWB
                            + (uint32_t)((lane >> 3) & 1)*16 + kk*32;
                asm volatile("ldmatrix.sync.aligned.m8n8.x4.shared.b16 {%0,%1,%2,%3}, [%4];"
                    : "=r"(bfr[ng][0]), "=r"(bfr[ng][1]), "=r"(bfr[ng][2]), "=r"(bfr[ng][3])
                    : "r"(bd));
            }
            #pragma unroll
            for (int mt = 0; mt < 2; ++mt)
                #pragma unroll
                for (int nt = 0; nt < 4; ++nt) {
                    uint32_t b0 = bfr[nt >> 1][(nt & 1)*2 + 0];
                    uint32_t b1 = bfr[nt >> 1][(nt & 1)*2 + 1];
                    mma_bf16(acc[mt][nt], af[mt][0], af[mt][1], af[mt][2], af[mt][3], b0, b1);
                }
        }
    }

    int g = lane >> 2, t4 = lane & 3;
    size_t rowbase = (size_t)bm*128 + wm*32;
    int colbase = bn*128 + wn*32;
    #pragma unroll
    for (int mt = 0; mt < 2; ++mt) {
        #pragma unroll
        for (int nt = 0; nt < 4; ++nt) {
            size_t r0 = rowbase + mt*16 + g;
            int    c0 = colbase + nt*8 + 2*t4;
            float x0 = acc[mt][nt][0], y0 = acc[mt][nt][1];
            float x1 = acc[mt][nt][2], y1 = acc[mt][nt][3];
            if (mode == 2) {
                float bx = bias[c0], by = bias[c0+1];
                x0 = gelu_exact(x0 + bx); y0 = gelu_exact(y0 + by);
                x1 = gelu_exact(x1 + bx); y1 = gelu_exact(y1 + by);
            }
            *(__nv_bfloat162*)(C + r0*N + c0)     = __float22bfloat162_rn(make_float2(x0, y0));
            *(__nv_bfloat162*)(C + (r0+8)*N + c0) = __float22bfloat162_rn(make_float2(x1, y1));
        }
    }
}

// ------- k-softmax(seq) + ctx = k^T v (per b,h): no-max softmax, __expf -----
#define KST 36
__global__ void __launch_bounds__(256) ctx_kernel(
    const __nv_bfloat16* __restrict__ QKV, float* __restrict__ CTX)
{
    __shared__ float Ks[SEQ][KST];
    __shared__ float red[8][DH];
    __shared__ float colinv[DH];
    int bh = blockIdx.x; int b = bh >> 3; int h = bh & 7;
    int tid = threadIdx.x;
    int d = tid & 31; int s = tid >> 5;
    const __nv_bfloat16* Kb = QKV + (size_t)b*SEQ*NQKV + 256 + h*DH;

    for (int i = tid; i < SEQ*DH; i += 256) {
        int n = i >> 5; int dd = i & 31;
        Ks[n][dd] = __bfloat162float(Kb[(size_t)n*NQKV + dd]);
    }
    __syncthreads();

    float sm = 0.f;
    for (int n = s; n < SEQ; n += 8) {
        float e = __expf(Ks[n][d]);
        Ks[n][d] = e; sm += e;
    }
    red[s][d] = sm;
    __syncthreads();
    if (tid < 32) {
        float ss = 0.f;
        #pragma unroll
        for (int i = 0; i < 8; ++i) ss += red[i][d];
        colinv[d] = 1.0f / ss;
    }
    __syncthreads();

    int e2 = tid & 31; int dbase = (tid >> 5) << 2;
    const __nv_bfloat16* Vb = QKV + (size_t)b*SEQ*NQKV + 512 + h*DH;
    float a0=0,a1=0,a2=0,a3=0;
    for (int n = 0; n < SEQ; ++n) {
        float vv = __bfloat162float(Vb[(size_t)n*NQKV + e2]);
        float4 kq = *(const float4*)&Ks[n][dbase];
        a0 = fmaf(kq.x, vv, a0);
        a1 = fmaf(kq.y, vv, a1);
        a2 = fmaf(kq.z, vv, a2);
        a3 = fmaf(kq.w, vv, a3);
    }
    float* Cb = CTX + (size_t)bh*DH*DH;
    Cb[(dbase+0)*DH + e2] = a0 * colinv[dbase+0];
    Cb[(dbase+1)*DH + e2] = a1 * colinv[dbase+1];
    Cb[(dbase+2)*DH + e2] = a2 * colinv[dbase+2];
    Cb[(dbase+3)*DH + e2] = a3 * colinv[dbase+3];
}

// ---------------- q-softmax(dh)*scale + o = q @ ctx (per b,h), __expf -------
__global__ void __launch_bounds__(256) attnout_kernel(
    const __nv_bfloat16* __restrict__ QKV, const float* __restrict__ CTX,
    __nv_bfloat16* __restrict__ O)
{
    __shared__ float ctxs[DH][DH];
    int bh = blockIdx.x; int b = bh >> 3; int h = bh & 7;
    int tid = threadIdx.x;
    for (int i = tid; i < DH*DH; i += 256)
        ctxs[i >> 5][i & 31] = CTX[(size_t)bh*DH*DH + i];
    __syncthreads();

    for (int n = tid; n < SEQ; n += 256) {
        const __nv_bfloat16* qr = QKV + ((size_t)b*SEQ + n)*NQKV + h*DH;
        float qv[DH];
        const uint4* q4 = (const uint4*)qr;
        #pragma unroll
        for (int i = 0; i < 4; ++i) {
            uint4 u = q4[i];
            uint32_t w[4] = {u.x, u.y, u.z, u.w};
            #pragma unroll
            for (int j = 0; j < 4; ++j) {
                float2 p = __bfloat1622float2(*reinterpret_cast<__nv_bfloat162*>(&w[j]));
                qv[i*8 + j*2]     = p.x;
                qv[i*8 + j*2 + 1] = p.y;
            }
        }
        float smq = 0.f;
        #pragma unroll
        for (int i = 0; i < 32; ++i) { qv[i] = __expf(qv[i]); smq += qv[i]; }
        float inv = 0.17677669529663687f / smq;
        float out[DH];
        #pragma unroll
        for (int j = 0; j < 32; ++j) out[j] = 0.f;
        #pragma unroll
        for (int dd = 0; dd < 32; ++dd) {
            float qd = qv[dd] * inv;
            #pragma unroll
            for (int j = 0; j < 32; ++j) out[j] = fmaf(qd, ctxs[dd][j], out[j]);
        }
        __nv_bfloat16* orow = O + ((size_t)b*SEQ + n)*EE + h*DH;
        #pragma unroll
        for (int i = 0; i < 4; ++i) {
            __nv_bfloat162 o2[4];
            #pragma unroll
            for (int j = 0; j < 4; ++j)
                o2[j] = __float22bfloat162_rn(make_float2(out[i*8+j*2], out[i*8+j*2+1]));
            *(uint4*)(orow + i*8) = *(uint4*)o2;
        }
    }
}

// ---------------- outputs (two-stage) ----------------
__global__ void res_copy_part_kernel(const float* __restrict__ H,
                                     const __nv_bfloat16* __restrict__ D,
                                     const float* __restrict__ bias,
                                     float* __restrict__ out, size_t meanN,
                                     float* __restrict__ part)
{
    int b = blockIdx.x, z = blockIdx.y, e = threadIdx.x;
    float bv = bias[e];
    float s = 0.f;
    int n0 = z * (SEQ/4), n1 = n0 + (SEQ/4);
    const float* hp = H + ((size_t)b*SEQ + n0)*EE + e;
    const __nv_bfloat16* dp = D + ((size_t)b*SEQ + n0)*EE + e;
    float* op = out + meanN + ((size_t)b*SEQ + n0)*EE + e;
    for (int n = n0; n < n1; ++n) {
        float v = *hp + __bfloat162float(*dp) + bv;
        *op = v;
        s += v;
        hp += EE; dp += EE; op += EE;
    }
    part[((size_t)b*4 + z)*EE + e] = s;
}

__global__ void mean_reduce_kernel(const float* __restrict__ part,
                                   float* __restrict__ out)
{
    int b = blockIdx.x, e = threadIdx.x;
    const float* p = part + (size_t)b*4*EE + e;
    out[(size_t)b*EE + e] = (p[0] + p[EE] + p[2*EE] + p[3*EE]) * (1.0f/(float)SEQ);
}

__global__ void resadd_kernel(float* __restrict__ H, const __nv_bfloat16* __restrict__ D,
                              const float* __restrict__ bias, int rows)
{
    int w    = (blockIdx.x * blockDim.x + threadIdx.x) >> 5;
    int lane = threadIdx.x & 31;
    if (w >= rows) return;
    float* hr = H + (size_t)w*EE + lane*8;
    const __nv_bfloat16* dr = D + (size_t)w*EE + lane*8;
    float v[8];
    *(float4*)&v[0] = *(const float4*)(hr);
    *(float4*)&v[4] = *(const float4*)(hr + 4);
    uint4 du = *(const uint4*)dr;
    uint32_t dw[4] = {du.x, du.y, du.z, du.w};
    #pragma unroll
    for (int j = 0; j < 4; ++j) {
        float2 p = __bfloat1622float2(*reinterpret_cast<__nv_bfloat162*>(&dw[j]));
        v[2*j]   += p.x + bias[lane*8 + 2*j];
        v[2*j+1] += p.y + bias[lane*8 + 2*j+1];
    }
    *(float4*)(hr)     = *(float4*)&v[0];
    *(float4*)(hr + 4) = *(float4*)&v[4];
}

__global__ void mean_kernel(const float* __restrict__ H, float* __restrict__ out)
{
    int b = blockIdx.x, e = threadIdx.x;
    float s = 0.f;
    for (int n = 0; n < SEQ; ++n) s += H[((size_t)b*SEQ + n)*EE + e];
    out[(size_t)b*EE + e] = s * (1.0f/(float)SEQ);
}

__global__ void copy4_kernel(const float4* __restrict__ src, float4* __restrict__ dst,
                             size_t n4)
{
    size_t i = (size_t)blockIdx.x*256 + threadIdx.x;
    if (i < n4) dst[i] = src[i];
}

// ---------------- host ----------------
extern "C" void kernel_launch(void* const* d_in, const int* in_sizes, int n_in,
                              void* d_out, int out_size)
{
    const float* x     = (const float*)d_in[0];
    const int*   noff  = (const int*)  d_in[1];
    const float* projW = (const float*)d_in[2];
    const float* projb = (const float*)d_in[3];
    const float* chan  = (const float*)d_in[4];
    const float* Wq    = (const float*)d_in[5];
    const float* Wk    = (const float*)d_in[6];
    const float* Wv    = (const float*)d_in[7];
    const float* Wo    = (const float*)d_in[8];
    const float* bo    = (const float*)d_in[9];
    const float* ln1g  = (const float*)d_in[10];
    const float* ln1b  = (const float*)d_in[11];
    const float* ln2g  = (const float*)d_in[12];
    const float* ln2b  = (const float*)d_in[13];
    const float* W1    = (const float*)d_in[14];
    const float* b1    = (const float*)d_in[15];
    const float* W2    = (const float*)d_in[16];
    const float* b2    = (const float*)d_in[17];

    int Bn = in_sizes[0] / (CC*TT);
    int M  = Bn * SEQ;

    float *H, *CX;
    __nv_bfloat16 *Yb, *QKV, *Ob, *FFb, *Wt, *Db;
    cudaGetSymbolAddress((void**)&H,   g_H);
    cudaGetSymbolAddress((void**)&Yb,  g_Yb);
    cudaGetSymbolAddress((void**)&QKV, g_QKV);
    cudaGetSymbolAddress((void**)&Ob,  g_Ob);
    cudaGetSymbolAddress((void**)&FFb, g_FFb);
    cudaGetSymbolAddress((void**)&CX,  g_CTX);
    cudaGetSymbolAddress((void**)&Wt,  g_Wt);
    cudaGetSymbolAddress((void**)&Db,  g_D);

    cudaFuncSetAttribute(mma_gemm_kernel,
        cudaFuncAttributeMaxDynamicSharedMemorySize, GSMEM);

    setup_kernel<<<dim3(32,32,25), dim3(32,8)>>>(Wq, Wk, Wv, Wo, W1, W2);
    embed_ln_kernel<<<M/8, 256>>>(x, noff, projW, projb, chan, ln1g, ln1b);

    dim3 gQKV(NQKV/128, M/128);
    dim3 gE  (EE/128,   M/128);
    dim3 gF  (FF4/128,  M/128);
    int lnBlocks = (M + 7) / 8;

    for (int l = 0; l < DEPTH; ++l) {
        __nv_bfloat16* base = Wt + (size_t)l * LWT;
        if (l > 0)
            resln_kernel<<<lnBlocks, 256>>>(H, Db, b2 + (size_t)(l-1)*EE, Yb,
                                            ln1g + l*EE, ln1b + l*EE, M);
        mma_gemm_kernel<<<gQKV, 512, GSMEM>>>(Yb, base, QKV, nullptr, M, NQKV, EE, 0);
        ctx_kernel<<<Bn*HH, 256>>>(QKV, CX);
        attnout_kernel<<<Bn*HH, 256>>>(QKV, CX, Ob);
        mma_gemm_kernel<<<gE, 512, GSMEM>>>(Ob, base+196608, Db, nullptr, M, EE, EE, 0);
        resln_kernel<<<lnBlocks, 256>>>(H, Db, bo + (size_t)l*EE, Yb,
                                        ln2g + l*EE, ln2b + l*EE, M);
        mma_gemm_kernel<<<gF, 512, GSMEM>>>(Yb,  base+262144, FFb, b1 + (size_t)l*FF4, M, FF4, EE, 2);
        mma_gemm_kernel<<<gE, 512, GSMEM>>>(FFb, base+524288, Db, nullptr, M, EE, FF4, 0);
    }

    float* out = (float*)d_out;
    size_t meanN = (size_t)Bn * EE;
    size_t hN    = (size_t)M * EE;
    size_t outN  = (size_t)out_size;
    const float* lastBias = b2 + (size_t)(DEPTH-1)*EE;
    if (outN >= meanN + hN) {
        res_copy_part_kernel<<<dim3(Bn,4), EE>>>(H, Db, lastBias, out, meanN, CX);
        mean_reduce_kernel<<<Bn, EE>>>(CX, out);
    } else if (outN >= hN) {
        resadd_kernel<<<lnBlocks, 256>>>(H, Db, lastBias, M);
        copy4_kernel<<<(unsigned)((hN/4 + 255)/256), 256>>>(
            (const float4*)H, (float4*)out, hN/4);
    } else {
        resadd_kernel<<<lnBlocks, 256>>>(H, Db, lastBias, M);
        mean_kernel<<<Bn, EE>>>(H, out);
    }
}

// round 16
// speedup vs baseline: 1.0121x; 1.0121x over previous
#include <cuda_runtime.h>
#include <cuda_bf16.h>
#include <math.h>
#include <stdint.h>

// ---------------- problem constants ----------------
#define CC    16
#define TT    2000
#define EE    256
#define NFFT  200
#define HOPL  100
#define NF    101
#define NFR   19
#define SEQ   (CC*NFR)   // 304
#define DEPTH 4
#define FF4   1024
#define HH    8
#define DH    32
#define BMAX  256
#define MMAX  (BMAX*SEQ)   // 77824
#define NQKV  768

// ---------------- device scratch ----------------
__device__ float          g_H  [ (size_t)MMAX*EE ];
__device__ __nv_bfloat16  g_Yb [ (size_t)MMAX*EE ];
__device__ __nv_bfloat16  g_QKV[ (size_t)MMAX*NQKV ];
__device__ __nv_bfloat16  g_Ob [ (size_t)MMAX*EE ];
__device__ __nv_bfloat16  g_FFb[ (size_t)MMAX*FF4 ];
__device__ __nv_bfloat16  g_D  [ (size_t)MMAX*EE ];
__device__ float          g_CTX[ (size_t)BMAX*HH*DH*DH ];
__device__ float g_cosT[ NFFT*NF ];
__device__ float g_sinT[ NFFT*NF ];
__device__ float g_win [ NFFT ];
__device__ float g_pe  [ NFR*EE ];
#define LWT  (4*65536 + 262144 + 262144)
__device__ __nv_bfloat16 g_Wt[ (size_t)DEPTH * LWT ];

__device__ __forceinline__ uint32_t smem_u32(const void* p) {
    uint32_t a;
    asm("{ .reg .u64 t; cvta.to.shared.u64 t, %1; cvt.u32.u64 %0, t; }" : "=r"(a) : "l"(p));
    return a;
}

// ------------- ONE setup kernel: transposes + twiddles + PE table -----------
__device__ __forceinline__ void transpose_tile(
    const float* __restrict__ s, __nv_bfloat16* __restrict__ d,
    int R, int C, int bx, int by, float tsh[32][33])
{
    int x = threadIdx.x, y = threadIdx.y;
    #pragma unroll
    for (int i = 0; i < 32; i += 8)
        tsh[y + i][x] = s[(size_t)(by*32 + y + i) * C + bx*32 + x];
    __syncthreads();
    #pragma unroll
    for (int i = 0; i < 32; i += 8)
        d[(size_t)(bx*32 + y + i) * R + by*32 + x] = __float2bfloat16_rn(tsh[x][y + i]);
}

__global__ void setup_kernel(const float* Wq, const float* Wk,
                             const float* Wv, const float* Wo,
                             const float* W1, const float* W2)
{
    __shared__ float t[32][33];
    int z = blockIdx.z;
    int bx = blockIdx.x, by = blockIdx.y;
    if (z < 16) {
        if (bx >= 8 || by >= 8) return;
        int l = z >> 2, which = z & 3;
        const float* srcs[4] = {Wq, Wk, Wv, Wo};
        const float* s = srcs[which] + (size_t)l * 65536;
        __nv_bfloat16* d = g_Wt + (size_t)l * LWT + (size_t)which * 65536;
        transpose_tile(s, d, 256, 256, bx, by, t);
    } else if (z < 20) {
        if (by >= 8) return;
        int l = z - 16;
        const float* s = W1 + (size_t)l * 262144;
        __nv_bfloat16* d = g_Wt + (size_t)l * LWT + 262144;
        transpose_tile(s, d, 256, 1024, bx, by, t);
    } else if (z < 24) {
        if (bx >= 8) return;
        int l = z - 20;
        const float* s = W2 + (size_t)l * 262144;
        __nv_bfloat16* d = g_Wt + (size_t)l * LWT + 524288;
        transpose_tile(s, d, 1024, 256, bx, by, t);
    } else {
        if (bx >= 8 || by >= 8) return;
        int tid = threadIdx.y * 32 + threadIdx.x;
        int bid = by * 8 + bx;
        int i0  = bid * 256 + tid;
        #pragma unroll
        for (int rep = 0; rep < 2; ++rep) {
            int i = i0 + rep * 16384;
            if (i < NFFT*NF) {
                int n = i / NF, k = i % NF;
                int m = (k * n) % NFFT;
                float a = (float)m / 100.0f;
                g_cosT[i] = cospif(a);
                g_sinT[i] = sinpif(a);
            }
        }
        if (i0 < NFFT) g_win[i0] = 0.5f * (1.0f - cospif((float)i0 / 100.0f));
        if (i0 < NFR*EE) {
            int f = i0 / EE, e = i0 % EE;
            int j2 = e & ~1;
            float dv = expf((float)j2 * (-9.210340371976184f / (float)EE));
            float arg = (float)f * dv;
            g_pe[i0] = (e & 1) ? cosf(arg) : sinf(arg);
        }
    }
}

// ------- STFT + |.| + projection + tokens + PE(table), fused layer-0 LN ----
__global__ void __launch_bounds__(256) embed_ln_kernel(
    const float* __restrict__ x, const int* __restrict__ noff_p,
    const float* __restrict__ projW, const float* __restrict__ projb,
    const float* __restrict__ chan_tok,
    const float* __restrict__ ln_g, const float* __restrict__ ln_b)
{
    __shared__ float frs[8][NFFT];
    __shared__ float pre[2][8][NF+1];
    __shared__ float pim[2][8][NF+1];
    __shared__ float mags[8][NF+3];
    __shared__ float hrows[8][EE];
    int tid  = threadIdx.x;
    int base = blockIdx.x * 8;

    for (int i = tid; i < 8*NFFT; i += 256) {
        int fl = i / NFFT, n = i % NFFT;
        int lid = base + fl;
        int b = lid / (CC*NFR); int rem = lid % (CC*NFR);
        int c = rem / NFR;      int f = rem % NFR;
        frs[fl][n] = x[((size_t)b*CC + c)*TT + f*HOPL + n] * g_win[n];
    }
    __syncthreads();

    if (tid < 2*NF) {
        int half = (tid >= NF) ? 1 : 0;
        int k = tid - half*NF;
        float re[8] = {0,0,0,0,0,0,0,0}, im[8] = {0,0,0,0,0,0,0,0};
        int n0 = half * 100;
        for (int n = n0; n < n0 + 100; ++n) {
            float cv = g_cosT[n*NF + k];
            float sv = g_sinT[n*NF + k];
            #pragma unroll
            for (int fl = 0; fl < 8; ++fl) {
                float fv = frs[fl][n];
                re[fl] = fmaf(fv, cv, re[fl]);
                im[fl] = fmaf(fv, sv, im[fl]);
            }
        }
        #pragma unroll
        for (int fl = 0; fl < 8; ++fl) {
            pre[half][fl][k] = re[fl];
            pim[half][fl][k] = im[fl];
        }
    }
    __syncthreads();

    if (tid < NF) {
        #pragma unroll
        for (int fl = 0; fl < 8; ++fl) {
            float re = pre[0][fl][tid] + pre[1][fl][tid];
            float im = pim[0][fl][tid] + pim[1][fl][tid];
            mags[fl][tid] = sqrtf(re*re + im*im);
        }
    }
    __syncthreads();

    int e = tid;
    float acc[8] = {0,0,0,0,0,0,0,0};
    for (int f = 0; f < NF; ++f) {
        float w = projW[f*EE + e];
        #pragma unroll
        for (int fl = 0; fl < 8; ++fl) acc[fl] = fmaf(mags[fl][f], w, acc[fl]);
    }
    int noff  = *noff_p;
    float pb  = projb[e];
    #pragma unroll
    for (int fl = 0; fl < 8; ++fl) {
        int lid = base + fl;
        int rem = lid % (CC*NFR);
        int c = rem / NFR; int f = rem % NFR;
        float pe  = g_pe[f*EE + e];
        float ct  = chan_tok[(size_t)(noff + c)*EE + e];
        float hv  = acc[fl] + pb + ct + pe;
        g_H[(size_t)lid*EE + e] = hv;
        hrows[fl][e] = hv;
    }
    __syncthreads();

    int w = tid >> 5, lane = tid & 31;
    float v[8]; float s = 0.f;
    #pragma unroll
    for (int i = 0; i < 8; ++i) { v[i] = hrows[w][lane + 32*i]; s += v[i]; }
    #pragma unroll
    for (int o = 16; o; o >>= 1) s += __shfl_xor_sync(0xffffffffu, s, o);
    float mu = s * (1.f/256.f);
    float q = 0.f;
    #pragma unroll
    for (int i = 0; i < 8; ++i) { float d = v[i]-mu; q = fmaf(d,d,q); }
    #pragma unroll
    for (int o = 16; o; o >>= 1) q += __shfl_xor_sync(0xffffffffu, q, o);
    float r = rsqrtf(q * (1.f/256.f) + 1e-5f);
    __nv_bfloat16* yr = g_Yb + (size_t)(base + w)*EE;
    #pragma unroll
    for (int i = 0; i < 8; ++i) {
        int c = lane + 32*i;
        yr[c] = __float2bfloat16_rn((v[i]-mu)*r*ln_g[c] + ln_b[c]);
    }
}

// ------- fused residual + LayerNorm: H += D + bias; Y = LN(H) ---------------
__global__ void resln_kernel(float* __restrict__ H, const __nv_bfloat16* __restrict__ D,
                             const float* __restrict__ bias,
                             __nv_bfloat16* __restrict__ Y,
                             const float* __restrict__ g, const float* __restrict__ b,
                             int rows)
{
    int w    = (blockIdx.x * blockDim.x + threadIdx.x) >> 5;
    int lane = threadIdx.x & 31;
    if (w >= rows) return;
    float* hr = H + (size_t)w*EE + lane*8;
    const __nv_bfloat16* dr = D + (size_t)w*EE + lane*8;
    float v[8];
    *(float4*)&v[0] = *(const float4*)(hr);
    *(float4*)&v[4] = *(const float4*)(hr + 4);
    uint4 du = *(const uint4*)dr;
    uint32_t dw[4] = {du.x, du.y, du.z, du.w};
    float bi[8];
    *(float4*)&bi[0] = *(const float4*)(bias + lane*8);
    *(float4*)&bi[4] = *(const float4*)(bias + lane*8 + 4);
    #pragma unroll
    for (int j = 0; j < 4; ++j) {
        float2 p = __bfloat1622float2(*reinterpret_cast<__nv_bfloat162*>(&dw[j]));
        v[2*j]   += p.x + bi[2*j];
        v[2*j+1] += p.y + bi[2*j+1];
    }
    *(float4*)(hr)     = *(float4*)&v[0];
    *(float4*)(hr + 4) = *(float4*)&v[4];

    float s = 0.f;
    #pragma unroll
    for (int i = 0; i < 8; ++i) s += v[i];
    #pragma unroll
    for (int o = 16; o; o >>= 1) s += __shfl_xor_sync(0xffffffffu, s, o);
    float mu = s * (1.f/256.f);
    float q = 0.f;
    #pragma unroll
    for (int i = 0; i < 8; ++i) { float d = v[i]-mu; q = fmaf(d,d,q); }
    #pragma unroll
    for (int o = 16; o; o >>= 1) q += __shfl_xor_sync(0xffffffffu, q, o);
    float r = rsqrtf(q * (1.f/256.f) + 1e-5f);
    float gg[8], bb[8];
    *(float4*)&gg[0] = *(const float4*)(g + lane*8);
    *(float4*)&gg[4] = *(const float4*)(g + lane*8 + 4);
    *(float4*)&bb[0] = *(const float4*)(b + lane*8);
    *(float4*)&bb[4] = *(const float4*)(b + lane*8 + 4);
    __nv_bfloat162 o2[4];
    #pragma unroll
    for (int i = 0; i < 4; ++i) {
        float y0 = (v[2*i]  -mu)*r*gg[2*i]   + bb[2*i];
        float y1 = (v[2*i+1]-mu)*r*gg[2*i+1] + bb[2*i+1];
        o2[i] = __float22bfloat162_rn(make_float2(y0, y1));
    }
    *(uint4*)(Y + (size_t)w*EE + lane*8) = *(uint4*)o2;
}

// ====== bf16 mma.sync GEMM, 8 warps (2x4), K-chunk 64, 3-stage cp.async =====
#define ROWB    144
#define TILEB   (128*ROWB)
#define STAGE_B (2*TILEB)
#define GSMEM   (3*STAGE_B)

__device__ __forceinline__ float gelu_exact(float x) {
    return 0.5f * x * (1.0f + erff(x * 0.70710678118654752f));
}

__device__ __forceinline__ void mma_bf16(float* c, uint32_t a0, uint32_t a1,
                                         uint32_t a2, uint32_t a3,
                                         uint32_t b0, uint32_t b1)
{
    asm volatile(
        "mma.sync.aligned.m16n8k16.row.col.f32.bf16.bf16.f32 "
        "{%0,%1,%2,%3}, {%4,%5,%6,%7}, {%8,%9}, {%0,%1,%2,%3};"
        : "+f"(c[0]), "+f"(c[1]), "+f"(c[2]), "+f"(c[3])
        : "r"(a0), "r"(a1), "r"(a2), "r"(a3), "r"(b0), "r"(b1));
}

__global__ void __launch_bounds__(256) mma_gemm_kernel(
    const __nv_bfloat16* __restrict__ A, const __nv_bfloat16* __restrict__ Bt,
    __nv_bfloat16* __restrict__ C, const float* __restrict__ bias,
    int M, int N, int K, int mode)
{
    extern __shared__ char smraw[];
    uint32_t sb = smem_u32(smraw);
    int tid = threadIdx.x, lane = tid & 31, wid = tid >> 5;
    int bm = blockIdx.y, bn = blockIdx.x;
    int wm = wid >> 2, wn = wid & 3;

    const __nv_bfloat16* Ag = A  + (size_t)bm * 128 * K;
    const __nv_bfloat16* Bg = Bt + (size_t)bn * 128 * K;

    float acc[4][4][4];
    #pragma unroll
    for (int mt = 0; mt < 4; ++mt)
        #pragma unroll
        for (int nt = 0; nt < 4; ++nt)
            #pragma unroll
            for (int r = 0; r < 4; ++r) acc[mt][nt][r] = 0.f;

    auto copy_stage = [&](int t, int s) {
        uint32_t base = sb + s * STAGE_B;
        #pragma unroll
        for (int i = 0; i < 4; ++i) {
            int idx = tid + i*256;
            int row = idx >> 3, q = idx & 7;
            const __nv_bfloat16* sa = Ag + (size_t)row * K + t*64 + q*8;
            const __nv_bfloat16* sbp = Bg + (size_t)row * K + t*64 + q*8;
            uint32_t dA = base + row*ROWB + q*16;
            uint32_t dB = base + TILEB + row*ROWB + q*16;
            asm volatile("cp.async.cg.shared.global [%0], [%1], 16;" :: "r"(dA), "l"(sa) : "memory");
            asm volatile("cp.async.cg.shared.global [%0], [%1], 16;" :: "r"(dB), "l"(sbp) : "memory");
        }
    };

    int nc = K >> 6;
    copy_stage(0, 0);
    asm volatile("cp.async.commit_group;" ::: "memory");
    if (nc > 1) copy_stage(1, 1);
    asm volatile("cp.async.commit_group;" ::: "memory");

    for (int t = 0; t < nc; ++t) {
        asm volatile("cp.async.wait_group 1;" ::: "memory");
        __syncthreads();
        if (t + 2 < nc) copy_stage(t + 2, (t + 2) % 3);
        asm volatile("cp.async.commit_group;" ::: "memory");

        int s = t % 3;
        uint32_t Abase = sb + s*STAGE_B + (wm*64)*ROWB;
        uint32_t Bbase = sb + s*STAGE_B + TILEB + (wn*32)*ROWB;
        #pragma unroll
        for (int kk = 0; kk < 4; ++kk) {
            uint32_t af[4][4], bfr[2][4];
            #pragma unroll
            for (int mt = 0; mt < 4; ++mt) {
                uint32_t ad = Abase + (uint32_t)(mt*16 + (lane & 15))*ROWB
                            + (uint32_t)(lane >> 4)*16 + kk*32;
                asm volatile("ldmatrix.sync.aligned.m8n8.x4.shared.b16 {%0,%1,%2,%3}, [%4];"
                    : "=r"(af[mt][0]), "=r"(af[mt][1]), "=r"(af[mt][2]), "=r"(af[mt][3])
                    : "r"(ad));
            }
            #pragma unroll
            for (int ng = 0; ng < 2; ++ng) {
                uint32_t bd = Bbase + (uint32_t)(ng*16 + (lane & 7) + ((lane >> 4) & 1)*8)*ROWB
                            + (uint32_t)((lane >> 3) & 1)*16 + kk*32;
                asm volatile("ldmatrix.sync.aligned.m8n8.x4.shared.b16 {%0,%1,%2,%3}, [%4];"
                    : "=r"(bfr[ng][0]), "=r"(bfr[ng][1]), "=r"(bfr[ng][2]), "=r"(bfr[ng][3])
                    : "r"(bd));
            }
            #pragma unroll
            for (int mt = 0; mt < 4; ++mt)
                #pragma unroll
                for (int nt = 0; nt < 4; ++nt) {
                    uint32_t b0 = bfr[nt >> 1][(nt & 1)*2 + 0];
                    uint32_t b1 = bfr[nt >> 1][(nt & 1)*2 + 1];
                    mma_bf16(acc[mt][nt], af[mt][0], af[mt][1], af[mt][2], af[mt][3], b0, b1);
                }
        }
    }

    int g = lane >> 2, t4 = lane & 3;
    size_t rowbase = (size_t)bm*128 + wm*64;
    int colbase = bn*128 + wn*32;
    #pragma unroll
    for (int mt = 0; mt < 4; ++mt) {
        #pragma unroll
        for (int nt = 0; nt < 4; ++nt) {
            size_t r0 = rowbase + mt*16 + g;
            int    c0 = colbase + nt*8 + 2*t4;
            float x0 = acc[mt][nt][0], y0 = acc[mt][nt][1];
            float x1 = acc[mt][nt][2], y1 = acc[mt][nt][3];
            if (mode == 2) {
                float bx = bias[c0], by = bias[c0+1];
                x0 = gelu_exact(x0 + bx); y0 = gelu_exact(y0 + by);
                x1 = gelu_exact(x1 + bx); y1 = gelu_exact(y1 + by);
            }
            *(__nv_bfloat162*)(C + r0*N + c0)     = __float22bfloat162_rn(make_float2(x0, y0));
            *(__nv_bfloat162*)(C + (r0+8)*N + c0) = __float22bfloat162_rn(make_float2(x1, y1));
        }
    }
}

// ------- k-softmax(seq) + ctx = k^T v: all-smem inner loop (bf16 K,V) -------
#define KSTB 40   // bf16 row stride (80 B): 8B-aligned quad reads, conflict-free
__global__ void __launch_bounds__(256) ctx_kernel(
    const __nv_bfloat16* __restrict__ QKV, float* __restrict__ CTX)
{
    __shared__ __nv_bfloat16 Ks[SEQ][KSTB];   // 24320 B  (exp(K))
    __shared__ __nv_bfloat16 Vs[SEQ][DH];     // 19456 B
    __shared__ float red[8][DH];
    __shared__ float colinv[DH];
    int bh = blockIdx.x; int b = bh >> 3; int h = bh & 7;
    int tid = threadIdx.x;
    int d = tid & 31; int s = tid >> 5;
    const __nv_bfloat16* Kb = QKV + (size_t)b*SEQ*NQKV + 256 + h*DH;
    const __nv_bfloat16* Vb = QKV + (size_t)b*SEQ*NQKV + 512 + h*DH;

    for (int i = tid; i < SEQ*DH; i += 256) {
        int n = i >> 5; int dd = i & 31;
        Ks[n][dd] = Kb[(size_t)n*NQKV + dd];
        Vs[n][dd] = Vb[(size_t)n*NQKV + dd];
    }
    __syncthreads();

    // exp in place (no max subtraction: |K| small, softmax shift-invariant)
    float sm = 0.f;
    for (int n = s; n < SEQ; n += 8) {
        float e = __expf(__bfloat162float(Ks[n][d]));
        Ks[n][d] = __float2bfloat16_rn(e);
        sm += e;
    }
    red[s][d] = sm;
    __syncthreads();
    if (tid < 32) {
        float ss = 0.f;
        #pragma unroll
        for (int i = 0; i < 8; ++i) ss += red[i][d];
        colinv[d] = 1.0f / ss;
    }
    __syncthreads();

    int e2 = tid & 31; int dbase = (tid >> 5) << 2;
    float a0=0,a1=0,a2=0,a3=0;
    for (int n = 0; n < SEQ; ++n) {
        float vv = __bfloat162float(Vs[n][e2]);
        uint2 kw = *(const uint2*)&Ks[n][dbase];   // 4 bf16, broadcast LDS.64
        float2 k01 = __bfloat1622float2(*reinterpret_cast<__nv_bfloat162*>(&kw.x));
        float2 k23 = __bfloat1622float2(*reinterpret_cast<__nv_bfloat162*>(&kw.y));
        a0 = fmaf(k01.x, vv, a0);
        a1 = fmaf(k01.y, vv, a1);
        a2 = fmaf(k23.x, vv, a2);
        a3 = fmaf(k23.y, vv, a3);
    }
    float* Cb = CTX + (size_t)bh*DH*DH;
    Cb[(dbase+0)*DH + e2] = a0 * colinv[dbase+0];
    Cb[(dbase+1)*DH + e2] = a1 * colinv[dbase+1];
    Cb[(dbase+2)*DH + e2] = a2 * colinv[dbase+2];
    Cb[(dbase+3)*DH + e2] = a3 * colinv[dbase+3];
}

// ---------------- q-softmax(dh)*scale + o = q @ ctx (per b,h), __expf -------
__global__ void __launch_bounds__(256) attnout_kernel(
    const __nv_bfloat16* __restrict__ QKV, const float* __restrict__ CTX,
    __nv_bfloat16* __restrict__ O)
{
    __shared__ float ctxs[DH][DH];
    int bh = blockIdx.x; int b = bh >> 3; int h = bh & 7;
    int tid = threadIdx.x;
    for (int i = tid; i < DH*DH; i += 256)
        ctxs[i >> 5][i & 31] = CTX[(size_t)bh*DH*DH + i];
    __syncthreads();

    for (int n = tid; n < SEQ; n += 256) {
        const __nv_bfloat16* qr = QKV + ((size_t)b*SEQ + n)*NQKV + h*DH;
        float qv[DH];
        const uint4* q4 = (const uint4*)qr;
        #pragma unroll
        for (int i = 0; i < 4; ++i) {
            uint4 u = q4[i];
            uint32_t w[4] = {u.x, u.y, u.z, u.w};
            #pragma unroll
            for (int j = 0; j < 4; ++j) {
                float2 p = __bfloat1622float2(*reinterpret_cast<__nv_bfloat162*>(&w[j]));
                qv[i*8 + j*2]     = p.x;
                qv[i*8 + j*2 + 1] = p.y;
            }
        }
        float smq = 0.f;
        #pragma unroll
        for (int i = 0; i < 32; ++i) { qv[i] = __expf(qv[i]); smq += qv[i]; }
        float inv = 0.17677669529663687f / smq;
        float out[DH];
        #pragma unroll
        for (int j = 0; j < 32; ++j) out[j] = 0.f;
        #pragma unroll
        for (int dd = 0; dd < 32; ++dd) {
            float qd = qv[dd] * inv;
            #pragma unroll
            for (int j = 0; j < 32; ++j) out[j] = fmaf(qd, ctxs[dd][j], out[j]);
        }
        __nv_bfloat16* orow = O + ((size_t)b*SEQ + n)*EE + h*DH;
        #pragma unroll
        for (int i = 0; i < 4; ++i) {
            __nv_bfloat162 o2[4];
            #pragma unroll
            for (int j = 0; j < 4; ++j)
                o2[j] = __float22bfloat162_rn(make_float2(out[i*8+j*2], out[i*8+j*2+1]));
            *(uint4*)(orow + i*8) = *(uint4*)o2;
        }
    }
}

// ---------------- outputs (two-stage) ----------------
__global__ void res_copy_part_kernel(const float* __restrict__ H,
                                     const __nv_bfloat16* __restrict__ D,
                                     const float* __restrict__ bias,
                                     float* __restrict__ out, size_t meanN,
                                     float* __restrict__ part)
{
    int b = blockIdx.x, z = blockIdx.y, e = threadIdx.x;
    float bv = bias[e];
    float s = 0.f;
    int n0 = z * (SEQ/4), n1 = n0 + (SEQ/4);
    const float* hp = H + ((size_t)b*SEQ + n0)*EE + e;
    const __nv_bfloat16* dp = D + ((size_t)b*SEQ + n0)*EE + e;
    float* op = out + meanN + ((size_t)b*SEQ + n0)*EE + e;
    for (int n = n0; n < n1; ++n) {
        float v = *hp + __bfloat162float(*dp) + bv;
        *op = v;
        s += v;
        hp += EE; dp += EE; op += EE;
    }
    part[((size_t)b*4 + z)*EE + e] = s;
}

__global__ void mean_reduce_kernel(const float* __restrict__ part,
                                   float* __restrict__ out)
{
    int b = blockIdx.x, e = threadIdx.x;
    const float* p = part + (size_t)b*4*EE + e;
    out[(size_t)b*EE + e] = (p[0] + p[EE] + p[2*EE] + p[3*EE]) * (1.0f/(float)SEQ);
}

__global__ void resadd_kernel(float* __restrict__ H, const __nv_bfloat16* __restrict__ D,
                              const float* __restrict__ bias, int rows)
{
    int w    = (blockIdx.x * blockDim.x + threadIdx.x) >> 5;
    int lane = threadIdx.x & 31;
    if (w >= rows) return;
    float* hr = H + (size_t)w*EE + lane*8;
    const __nv_bfloat16* dr = D + (size_t)w*EE + lane*8;
    float v[8];
    *(float4*)&v[0] = *(const float4*)(hr);
    *(float4*)&v[4] = *(const float4*)(hr + 4);
    uint4 du = *(const uint4*)dr;
    uint32_t dw[4] = {du.x, du.y, du.z, du.w};
    #pragma unroll
    for (int j = 0; j < 4; ++j) {
        float2 p = __bfloat1622float2(*reinterpret_cast<__nv_bfloat162*>(&dw[j]));
        v[2*j]   += p.x + bias[lane*8 + 2*j];
        v[2*j+1] += p.y + bias[lane*8 + 2*j+1];
    }
    *(float4*)(hr)     = *(float4*)&v[0];
    *(float4*)(hr + 4) = *(float4*)&v[4];
}

__global__ void mean_kernel(const float* __restrict__ H, float* __restrict__ out)
{
    int b = blockIdx.x, e = threadIdx.x;
    float s = 0.f;
    for (int n = 0; n < SEQ; ++n) s += H[((size_t)b*SEQ + n)*EE + e];
    out[(size_t)b*EE + e] = s * (1.0f/(float)SEQ);
}

__global__ void copy4_kernel(const float4* __restrict__ src, float4* __restrict__ dst,
                             size_t n4)
{
    size_t i = (size_t)blockIdx.x*256 + threadIdx.x;
    if (i < n4) dst[i] = src[i];
}

// ---------------- host ----------------
extern "C" void kernel_launch(void* const* d_in, const int* in_sizes, int n_in,
                              void* d_out, int out_size)
{
    const float* x     = (const float*)d_in[0];
    const int*   noff  = (const int*)  d_in[1];
    const float* projW = (const float*)d_in[2];
    const float* projb = (const float*)d_in[3];
    const float* chan  = (const float*)d_in[4];
    const float* Wq    = (const float*)d_in[5];
    const float* Wk    = (const float*)d_in[6];
    const float* Wv    = (const float*)d_in[7];
    const float* Wo    = (const float*)d_in[8];
    const float* bo    = (const float*)d_in[9];
    const float* ln1g  = (const float*)d_in[10];
    const float* ln1b  = (const float*)d_in[11];
    const float* ln2g  = (const float*)d_in[12];
    const float* ln2b  = (const float*)d_in[13];
    const float* W1    = (const float*)d_in[14];
    const float* b1    = (const float*)d_in[15];
    const float* W2    = (const float*)d_in[16];
    const float* b2    = (const float*)d_in[17];

    int Bn = in_sizes[0] / (CC*TT);
    int M  = Bn * SEQ;

    float *H, *CX;
    __nv_bfloat16 *Yb, *QKV, *Ob, *FFb, *Wt, *Db;
    cudaGetSymbolAddress((void**)&H,   g_H);
    cudaGetSymbolAddress((void**)&Yb,  g_Yb);
    cudaGetSymbolAddress((void**)&QKV, g_QKV);
    cudaGetSymbolAddress((void**)&Ob,  g_Ob);
    cudaGetSymbolAddress((void**)&FFb, g_FFb);
    cudaGetSymbolAddress((void**)&CX,  g_CTX);
    cudaGetSymbolAddress((void**)&Wt,  g_Wt);
    cudaGetSymbolAddress((void**)&Db,  g_D);

    cudaFuncSetAttribute(mma_gemm_kernel,
        cudaFuncAttributeMaxDynamicSharedMemorySize, GSMEM);

    setup_kernel<<<dim3(32,32,25), dim3(32,8)>>>(Wq, Wk, Wv, Wo, W1, W2);
    embed_ln_kernel<<<M/8, 256>>>(x, noff, projW, projb, chan, ln1g, ln1b);

    dim3 gQKV(NQKV/128, M/128);
    dim3 gE  (EE/128,   M/128);
    dim3 gF  (FF4/128,  M/128);
    int lnBlocks = (M + 7) / 8;

    for (int l = 0; l < DEPTH; ++l) {
        __nv_bfloat16* base = Wt + (size_t)l * LWT;
        if (l > 0)
            resln_kernel<<<lnBlocks, 256>>>(H, Db, b2 + (size_t)(l-1)*EE, Yb,
                                            ln1g + l*EE, ln1b + l*EE, M);
        mma_gemm_kernel<<<gQKV, 256, GSMEM>>>(Yb, base, QKV, nullptr, M, NQKV, EE, 0);
        ctx_kernel<<<Bn*HH, 256>>>(QKV, CX);
        attnout_kernel<<<Bn*HH, 256>>>(QKV, CX, Ob);
        mma_gemm_kernel<<<gE, 256, GSMEM>>>(Ob, base+196608, Db, nullptr, M, EE, EE, 0);
        resln_kernel<<<lnBlocks, 256>>>(H, Db, bo + (size_t)l*EE, Yb,
                                        ln2g + l*EE, ln2b + l*EE, M);
        mma_gemm_kernel<<<gF, 256, GSMEM>>>(Yb,  base+262144, FFb, b1 + (size_t)l*FF4, M, FF4, EE, 2);
        mma_gemm_kernel<<<gE, 256, GSMEM>>>(FFb, base+524288, Db, nullptr, M, EE, FF4, 0);
    }

    float* out = (float*)d_out;
    size_t meanN = (size_t)Bn * EE;
    size_t hN    = (size_t)M * EE;
    size_t outN  = (size_t)out_size;
    const float* lastBias = b2 + (size_t)(DEPTH-1)*EE;
    if (outN >= meanN + hN) {
        res_copy_part_kernel<<<dim3(Bn,4), EE>>>(H, Db, lastBias, out, meanN, CX);
        mean_reduce_kernel<<<Bn, EE>>>(CX, out);
    } else if (outN >= hN) {
        resadd_kernel<<<lnBlocks, 256>>>(H, Db, lastBias, M);
        copy4_kernel<<<(unsigned)((hN/4 + 255)/256), 256>>>(
            (const float4*)H, (float4*)out, hN/4);
    } else {
        resadd_kernel<<<lnBlocks, 256>>>(H, Db, lastBias, M);
        mean_kernel<<<Bn, EE>>>(H, out);
    }
}